// round 12
// baseline (speedup 1.0000x reference)
#include <cuda_runtime.h>

// Problem constants
#define TT 512
#define DD 16
#define HH 48
#define NB 16
#define NBI 2          // batch per domain
#define NTHREADS 768   // 8 domains x 96 threads (3 warps)
#define NCTA 128

typedef unsigned long long ull;

// SMEM byte offsets
#define W1I_B 0                   // [8 kp][96 jj2][16B]
#define WR_B  12288               // [24 kp][96 jj2][3 mat][16B]
#define BB1_B 122880              // [96 jj2][16B] {b_g0,0,b_g1,0}
#define BB2_B 124416
#define H1_B  125952              // [2 buf][16 bb][48f]
#define H2_B  132096
#define XD_B  138240              // [2 buf][16 bb][16f]
#define SMEM_BYTES 140288

#define HROWB 192
#define HBUF  3072                // 16*192
#define XROWB 64
#define XBUF  1024                // 16*64

__device__ __forceinline__ float fsig(float x) {
    return __fdividef(1.0f, 1.0f + __expf(-x));
}
__device__ __forceinline__ float ftanh_(float x) {
    return __fdividef(2.0f, 1.0f + __expf(-2.0f * x)) - 1.0f;
}
__device__ __forceinline__ void ffma2(ull& a, ull w, ull h) {
    asm("fma.rn.f32x2 %0, %1, %2, %0;" : "+l"(a) : "l"(w), "l"(h));
}
__device__ __forceinline__ float2 unpk(ull v) {
    float2 r;
    asm("mov.b64 {%0, %1}, %2;" : "=f"(r.x), "=f"(r.y) : "l"(v));
    return r;
}
__device__ __forceinline__ ull pk2(float a, float b) {
    ull d;
    asm("mov.b64 %0, {%1, %2};" : "=l"(d) : "f"(a), "f"(b));
    return d;
}
__device__ __forceinline__ void d_bar(int id) {
    asm volatile("bar.sync %0, 96;" :: "r"(id) : "memory");
}

__global__ void __launch_bounds__(NTHREADS, 1)
lstm2_kernel(const float* __restrict__ x,
             const float* __restrict__ Wih0, const float* __restrict__ Whh0,
             const float* __restrict__ bih0, const float* __restrict__ bhh0,
             const float* __restrict__ Wih1, const float* __restrict__ Whh1,
             const float* __restrict__ bih1, const float* __restrict__ bhh1,
             const float* __restrict__ fcw,  const float* __restrict__ fcb,
             float* __restrict__ out)
{
    extern __shared__ char sm[];
    float* smf = (float*)sm;
    const int tid = threadIdx.x;

    // ---- repack W1I: [8kp][96jj2][16B] ----
    for (int i = tid; i < 8*96*4; i += NTHREADS) {
        int f = i & 3, jj2 = (i >> 2) % 96, kp = i / 384;
        int j = jj2 >> 1, gp = jj2 & 1;
        int gate = gp*2 + (f >> 1), k = kp*2 + (f & 1);
        smf[(W1I_B >> 2) + i] = Wih0[(gate*HH + j)*DD + k];
    }
    // ---- repack WR: [24kp][96jj2][3mat][16B] (Whh0, Wih1, Whh1) ----
    for (int i = tid; i < 24*96*3*4; i += NTHREADS) {
        int f = i & 3, m = (i >> 2) % 3, jj2 = (i / 12) % 96, kp = i / 1152;
        int j = jj2 >> 1, gp = jj2 & 1;
        int gate = gp*2 + (f >> 1), k = kp*2 + (f & 1);
        int r = (gate*HH + j)*HH + k;
        smf[(WR_B >> 2) + i] = (m == 0) ? Whh0[r] : (m == 1) ? Wih1[r] : Whh1[r];
    }
    // ---- biases ----
    for (int i = tid; i < 96*4; i += NTHREADS) {
        int f = i & 3, jj2 = i >> 2;
        int j = jj2 >> 1, gp = jj2 & 1;
        int gate = gp*2 + (f >> 1);
        float v1 = (f & 1) ? 0.f : (bih0[gate*HH + j] + bhh0[gate*HH + j]);
        float v2 = (f & 1) ? 0.f : (bih1[gate*HH + j] + bhh1[gate*HH + j]);
        smf[(BB1_B >> 2) + i] = v1;
        smf[(BB2_B >> 2) + i] = v2;
    }
    // ---- zero h region (both layers, both bufs) ----
    for (int i = tid; i < (2*HBUF + 2*HBUF) >> 2; i += NTHREADS)
        smf[(H1_B >> 2) + i] = 0.f;

    // ---- domain decomposition: 8 domains of 3 warps ----
    // domain q = w/3 -> warps on 3 different SMSPs; each SMSP hosts 6 domains
    const int w    = tid >> 5;
    const int lane = tid & 31;
    const int q    = w / 3;            // 0..7 = batch group
    const int wq   = w % 3;
    const int gp   = lane & 1;
    const int j    = wq * 16 + (lane >> 1);
    const int jj2  = j * 2 + gp;
    const int grp  = q;
    const int barid = 1 + q;
    const int qtid  = wq * 32 + lane;  // 0..95 within domain

    const float* xg = x + ((long)blockIdx.x * NB) * (long)(TT*DD);
    // per-domain x staging: 32 threads stage this domain's 2 batch rows
    const int xact = (qtid < 32);
    const int xb_  = q * 2 + (qtid >> 4);
    const int xd   = qtid & 15;
    const int xoff = xb_ * XROWB + xd * 4;

    if (xact)
        *(float*)(sm + XD_B + xoff) = xg[(long)xb_*(TT*DD) + xd];
    __syncthreads();

    const char* pWI = sm + W1I_B + jj2*16;
    const char* pWR = sm + WR_B + jj2*48;
    const ulonglong2 b1 = *(const ulonglong2*)(sm + BB1_B + jj2*16);
    const ulonglong2 b2 = *(const ulonglong2*)(sm + BB2_B + jj2*16);

    float c1 = 0.f, c2 = 0.f;
    const int hoff = (grp*2 + gp) * HROWB + j*4;   // this thread's h store slot

    for (int t = 0; t <= TT; ++t) {
        const int cur = t & 1, prv = cur ^ 1;

        float xpre = 0.f;
        if (t + 1 < TT && xact)
            xpre = xg[(long)xb_*(TT*DD) + (long)(t+1)*DD + xd];

        ull a1I[NBI], a1F[NBI], a2I[NBI], a2F[NBI];
        #pragma unroll
        for (int bb = 0; bb < NBI; ++bb) {
            a1I[bb] = b1.x; a1F[bb] = b1.y;
            a2I[bb] = b2.x; a2F[bb] = b2.y;
        }

        // ===== layer1 input: x (k-parity packed, broadcast loads) =====
        {
            const char* xb = sm + XD_B + cur*XBUF + grp*2*XROWB;
            #pragma unroll
            for (int kx = 0; kx < 4; ++kx) {
                const ulonglong2 w0 = *(const ulonglong2*)(pWI + (2*kx  )*1536);
                const ulonglong2 w1 = *(const ulonglong2*)(pWI + (2*kx+1)*1536);
                #pragma unroll
                for (int bb = 0; bb < NBI; ++bb) {
                    const ulonglong2 xv = *(const ulonglong2*)(xb + bb*XROWB + kx*16);
                    ffma2(a1I[bb], w0.x, xv.x); ffma2(a1F[bb], w0.y, xv.x);
                    ffma2(a1I[bb], w1.x, xv.y); ffma2(a1F[bb], w1.y, xv.y);
                }
            }
        }

        // ===== fused recurrent: W1R@h1[t-1], W2I@h1[t-1], W2R@h2[t-2] =====
        {
            const char* h1b = sm + H1_B + prv*HBUF + grp*2*HROWB;
            const char* h2b = sm + H2_B + cur*HBUF + grp*2*HROWB;
            #pragma unroll 4
            for (int kb = 0; kb < 12; ++kb) {
                const char* wb = pWR + kb*9216;
                const ulonglong2 wa0 = *(const ulonglong2*)(wb);
                const ulonglong2 wb0 = *(const ulonglong2*)(wb + 16);
                const ulonglong2 wc0 = *(const ulonglong2*)(wb + 32);
                const ulonglong2 wa1 = *(const ulonglong2*)(wb + 4608);
                const ulonglong2 wb1 = *(const ulonglong2*)(wb + 4624);
                const ulonglong2 wc1 = *(const ulonglong2*)(wb + 4640);
                #pragma unroll
                for (int bb = 0; bb < NBI; ++bb) {
                    const ulonglong2 h1v = *(const ulonglong2*)(h1b + bb*HROWB + kb*16);
                    const ulonglong2 h2v = *(const ulonglong2*)(h2b + bb*HROWB + kb*16);
                    ffma2(a1I[bb], wa0.x, h1v.x); ffma2(a1F[bb], wa0.y, h1v.x);
                    ffma2(a1I[bb], wa1.x, h1v.y); ffma2(a1F[bb], wa1.y, h1v.y);
                    ffma2(a2I[bb], wb0.x, h1v.x); ffma2(a2F[bb], wb0.y, h1v.x);
                    ffma2(a2I[bb], wb1.x, h1v.y); ffma2(a2F[bb], wb1.y, h1v.y);
                    ffma2(a2I[bb], wc0.x, h2v.x); ffma2(a2F[bb], wc0.y, h2v.x);
                    ffma2(a2I[bb], wc1.x, h2v.y); ffma2(a2F[bb], wc1.y, h2v.y);
                }
            }
        }

        char* h1n = sm + H1_B + cur*HBUF;
        char* h2n = sm + H2_B + prv*HBUF;

        // horizontal sums -> p[bb] = {gate0_sum, gate1_sum} for bb=0,1
        // one shfl/layer: send p[1-gp], receive partner's -> complete gates of bb=gp
        if (t > 0 && t < TT) {
            ull p1[2], p2[2];
            #pragma unroll
            for (int bb = 0; bb < 2; ++bb) {
                float2 u1I = unpk(a1I[bb]), u1F = unpk(a1F[bb]);
                float2 u2I = unpk(a2I[bb]), u2F = unpk(a2F[bb]);
                p1[bb] = pk2(u1I.x + u1I.y, u1F.x + u1F.y);
                p2[bb] = pk2(u2I.x + u2I.y, u2F.x + u2F.y);
            }
            ull r1 = __shfl_xor_sync(0xFFFFFFFFu, gp ? p1[0] : p1[1], 1);
            ull r2 = __shfl_xor_sync(0xFFFFFFFFu, gp ? p2[0] : p2[1], 1);
            float2 pIF1 = unpk(gp ? r1 : p1[0]);
            float2 pGO1 = unpk(gp ? p1[1] : r1);
            float2 pIF2 = unpk(gp ? r2 : p2[0]);
            float2 pGO2 = unpk(gp ? p2[1] : r2);
            float iv1 = fsig(pIF1.x), iv2 = fsig(pIF2.x);
            float fv1 = fsig(pIF1.y), fv2 = fsig(pIF2.y);
            float gv1 = ftanh_(pGO1.x), gv2 = ftanh_(pGO2.x);
            float ov1 = fsig(pGO1.y),  ov2 = fsig(pGO2.y);
            c1 = fmaf(fv1, c1, iv1 * gv1);
            c2 = fmaf(fv2, c2, iv2 * gv2);
            *(float*)(h1n + hoff) = ov1 * ftanh_(c1);
            *(float*)(h2n + hoff) = ov2 * ftanh_(c2);
        } else if (t < TT) {
            // t == 0: layer1 only
            ull p1[2];
            #pragma unroll
            for (int bb = 0; bb < 2; ++bb) {
                float2 uI = unpk(a1I[bb]), uF = unpk(a1F[bb]);
                p1[bb] = pk2(uI.x + uI.y, uF.x + uF.y);
            }
            ull r1 = __shfl_xor_sync(0xFFFFFFFFu, gp ? p1[0] : p1[1], 1);
            float2 pIF = unpk(gp ? r1 : p1[0]);
            float2 pGO = unpk(gp ? p1[1] : r1);
            float iv = fsig(pIF.x), fv = fsig(pIF.y);
            float gv = ftanh_(pGO.x), ov = fsig(pGO.y);
            c1 = fmaf(fv, c1, iv * gv);
            *(float*)(h1n + hoff) = ov * ftanh_(c1);
        } else {
            // t == TT: layer2 only
            ull p2[2];
            #pragma unroll
            for (int bb = 0; bb < 2; ++bb) {
                float2 uI = unpk(a2I[bb]), uF = unpk(a2F[bb]);
                p2[bb] = pk2(uI.x + uI.y, uF.x + uF.y);
            }
            ull r2 = __shfl_xor_sync(0xFFFFFFFFu, gp ? p2[0] : p2[1], 1);
            float2 pIF = unpk(gp ? r2 : p2[0]);
            float2 pGO = unpk(gp ? p2[1] : r2);
            float iv = fsig(pIF.x), fv = fsig(pIF.y);
            float gv = ftanh_(pGO.x), ov = fsig(pGO.y);
            c2 = fmaf(fv, c2, iv * gv);
            *(float*)(h2n + hoff) = ov * ftanh_(c2);
        }

        if (t + 1 < TT && xact)
            *(float*)(sm + XD_B + prv*XBUF + xoff) = xpre;

        d_bar(barid);
    }

    __syncthreads();
    // ===== final FC + sigmoid: h2[511] in buf 1 =====
    if (tid < NB) {
        const float* h2f = (const float*)(sm + H2_B + HBUF + tid*HROWB);
        float acc = fcb[0];
        #pragma unroll
        for (int jj = 0; jj < HH; ++jj)
            acc = fmaf(h2f[jj], fcw[jj], acc);
        out[blockIdx.x * NB + tid] = fsig(acc);
    }
}

extern "C" void kernel_launch(void* const* d_in, const int* in_sizes, int n_in,
                              void* d_out, int out_size) {
    (void)in_sizes; (void)n_in; (void)out_size;
    cudaFuncSetAttribute(lstm2_kernel,
                         cudaFuncAttributeMaxDynamicSharedMemorySize, SMEM_BYTES);
    lstm2_kernel<<<NCTA, NTHREADS, SMEM_BYTES>>>(
        (const float*)d_in[0],
        (const float*)d_in[1], (const float*)d_in[2],
        (const float*)d_in[3], (const float*)d_in[4],
        (const float*)d_in[5], (const float*)d_in[6],
        (const float*)d_in[7], (const float*)d_in[8],
        (const float*)d_in[9], (const float*)d_in[10],
        (float*)d_out);
}

// round 13
// speedup vs baseline: 1.0717x; 1.0717x over previous
#include <cuda_runtime.h>

// Problem constants
#define TT 512
#define DD 16
#define HH 48
#define NB 16
#define NBI 8          // batch per domain (2 domains of 192 threads)
#define NTHREADS 384   // 96 jj2 x 2 grp x 2 kh ; 12 warps
#define NCTA 128

typedef unsigned long long ull;

// SMEM byte offsets
#define W1I_B 0                   // [8 kp][96 jj2][16B]
#define WR_B  12288               // [24 kp][96 jj2][3 mat][16B]
#define BB1_B 122880              // [96 jj2][16B] {b_g0,0,b_g1,0}
#define BB2_B 124416
#define H1_B  125952              // [2 buf][16 bb][48f]
#define H2_B  132096
#define XD_B  138240              // [2 buf][16 bb][16f]
#define SMEM_BYTES 140288

#define HROWB 192
#define HBUF  3072
#define XROWB 64
#define XBUF  1024

__device__ __forceinline__ float fsig(float x) {
    return __fdividef(1.0f, 1.0f + __expf(-x));
}
__device__ __forceinline__ float ftanh_(float x) {
    return __fdividef(2.0f, 1.0f + __expf(-2.0f * x)) - 1.0f;
}
__device__ __forceinline__ void ffma2(ull& a, ull w, ull h) {
    asm("fma.rn.f32x2 %0, %1, %2, %0;" : "+l"(a) : "l"(w), "l"(h));
}
__device__ __forceinline__ ull add2(ull a, ull b) {
    ull d;
    asm("add.rn.f32x2 %0, %1, %2;" : "=l"(d) : "l"(a), "l"(b));
    return d;
}
__device__ __forceinline__ float2 unpk(ull v) {
    float2 r;
    asm("mov.b64 {%0, %1}, %2;" : "=f"(r.x), "=f"(r.y) : "l"(v));
    return r;
}
__device__ __forceinline__ ull pk2(float a, float b) {
    ull d;
    asm("mov.b64 %0, {%1, %2};" : "=l"(d) : "f"(a), "f"(b));
    return d;
}
__device__ __forceinline__ void d_bar(int id) {
    asm volatile("bar.sync %0, 192;" :: "r"(id) : "memory");
}

__global__ void __launch_bounds__(NTHREADS, 1)
lstm2_kernel(const float* __restrict__ x,
             const float* __restrict__ Wih0, const float* __restrict__ Whh0,
             const float* __restrict__ bih0, const float* __restrict__ bhh0,
             const float* __restrict__ Wih1, const float* __restrict__ Whh1,
             const float* __restrict__ bih1, const float* __restrict__ bhh1,
             const float* __restrict__ fcw,  const float* __restrict__ fcb,
             float* __restrict__ out)
{
    extern __shared__ char sm[];
    float* smf = (float*)sm;
    const int tid = threadIdx.x;

    // ---- repack W1I: [8kp][96jj2][16B] = {wg0_k, wg0_k1, wg1_k, wg1_k1} ----
    for (int i = tid; i < 8*96*4; i += NTHREADS) {
        int f = i & 3, jj2 = (i >> 2) % 96, kp = i / 384;
        int jx = jj2 >> 1, gpx = jj2 & 1;
        int gate = gpx*2 + (f >> 1), k = kp*2 + (f & 1);
        smf[(W1I_B >> 2) + i] = Wih0[(gate*HH + jx)*DD + k];
    }
    // ---- repack WR: [24kp][96jj2][3mat][16B] (Whh0, Wih1, Whh1) ----
    for (int i = tid; i < 24*96*3*4; i += NTHREADS) {
        int f = i & 3, m = (i >> 2) % 3, jj2 = (i / 12) % 96, kp = i / 1152;
        int jx = jj2 >> 1, gpx = jj2 & 1;
        int gate = gpx*2 + (f >> 1), k = kp*2 + (f & 1);
        int r = (gate*HH + jx)*HH + k;
        smf[(WR_B >> 2) + i] = (m == 0) ? Whh0[r] : (m == 1) ? Wih1[r] : Whh1[r];
    }
    // ---- biases ----
    for (int i = tid; i < 96*4; i += NTHREADS) {
        int f = i & 3, jj2 = i >> 2;
        int jx = jj2 >> 1, gpx = jj2 & 1;
        int gate = gpx*2 + (f >> 1);
        float v1 = (f & 1) ? 0.f : (bih0[gate*HH + jx] + bhh0[gate*HH + jx]);
        float v2 = (f & 1) ? 0.f : (bih1[gate*HH + jx] + bhh1[gate*HH + jx]);
        smf[(BB1_B >> 2) + i] = v1;
        smf[(BB2_B >> 2) + i] = v2;
    }
    // ---- zero h region ----
    for (int i = tid; i < (4*HBUF) >> 2; i += NTHREADS)
        smf[(H1_B >> 2) + i] = 0.f;

    // ---- lane map: kh=b0, gp=b1, jl=b2-4 ; warp = grp*6 + wq ----
    const int w    = tid >> 5;
    const int lane = tid & 31;
    const int grp  = w / 6;            // 0..1 barrier domain / batch half
    const int wq   = w % 6;
    const int kh   = lane & 1;         // k-half
    const int gp   = (lane >> 1) & 1;  // gate pair
    const int jl   = lane >> 2;        // 0..7
    const int j    = wq * 8 + jl;
    const int jj2  = j * 2 + gp;
    const int barid = 1 + grp;
    const int qtid  = tid - grp * 192;

    const float* xg = x + ((long)blockIdx.x * NB) * (long)(TT*DD);
    // per-domain x staging: 128 threads stage the domain's 8 batch rows
    const int xact = (qtid < 128);
    const int xb_  = grp * 8 + (qtid >> 4);
    const int xd   = qtid & 15;
    const int xoff = xb_ * XROWB + xd * 4;

    if (xact)
        *(float*)(sm + XD_B + xoff) = xg[(long)xb_*(TT*DD) + xd];
    __syncthreads();

    // per-thread weight slices: kh selects the k-half (disjoint -> no redundancy)
    const char* pWI = sm + W1I_B + kh*(4*1536)  + jj2*16;
    const char* pWR = sm + WR_B  + kh*(12*4608) + jj2*48;
    ulonglong2 b1 = *(const ulonglong2*)(sm + BB1_B + jj2*16);
    ulonglong2 b2 = *(const ulonglong2*)(sm + BB2_B + jj2*16);
    if (kh) { b1.x = 0ULL; b1.y = 0ULL; b2.x = 0ULL; b2.y = 0ULL; }

    float c1[2] = {0.f, 0.f};
    float c2[2] = {0.f, 0.f};

    for (int t = 0; t <= TT; ++t) {
        const int cur = t & 1, prv = cur ^ 1;

        float xpre = 0.f;
        if (t + 1 < TT && xact)
            xpre = xg[(long)xb_*(TT*DD) + (long)(t+1)*DD + xd];

        ull a1G0[NBI], a1G1[NBI], a2G0[NBI], a2G1[NBI];
        #pragma unroll
        for (int bb = 0; bb < NBI; ++bb) {
            a1G0[bb] = b1.x; a1G1[bb] = b1.y;
            a2G0[bb] = b2.x; a2G1[bb] = b2.y;
        }

        // ===== layer1 input: x (this thread's k-half) =====
        {
            const char* xb = sm + XD_B + cur*XBUF + grp*(8*XROWB) + kh*32;
            #pragma unroll
            for (int kx = 0; kx < 2; ++kx) {
                const ulonglong2 w0 = *(const ulonglong2*)(pWI + (2*kx  )*1536);
                const ulonglong2 w1 = *(const ulonglong2*)(pWI + (2*kx+1)*1536);
                #pragma unroll
                for (int bb = 0; bb < NBI; ++bb) {
                    const ulonglong2 xv = *(const ulonglong2*)(xb + bb*XROWB + kx*16);
                    ffma2(a1G0[bb], w0.x, xv.x); ffma2(a1G1[bb], w0.y, xv.x);
                    ffma2(a1G0[bb], w1.x, xv.y); ffma2(a1G1[bb], w1.y, xv.y);
                }
            }
        }

        // ===== fused recurrent (k-half): W1R@h1[t-1], W2I@h1[t-1], W2R@h2[t-2] =====
        {
            const char* h1b = sm + H1_B + prv*HBUF + grp*(8*HROWB) + kh*96;
            const char* h2b = sm + H2_B + cur*HBUF + grp*(8*HROWB) + kh*96;
            #pragma unroll 3
            for (int kb = 0; kb < 6; ++kb) {
                const char* wb = pWR + kb*9216;
                const ulonglong2 wa0 = *(const ulonglong2*)(wb);
                const ulonglong2 wb0 = *(const ulonglong2*)(wb + 16);
                const ulonglong2 wc0 = *(const ulonglong2*)(wb + 32);
                const ulonglong2 wa1 = *(const ulonglong2*)(wb + 4608);
                const ulonglong2 wb1 = *(const ulonglong2*)(wb + 4624);
                const ulonglong2 wc1 = *(const ulonglong2*)(wb + 4640);
                #pragma unroll
                for (int bb = 0; bb < NBI; ++bb) {
                    const ulonglong2 h1v = *(const ulonglong2*)(h1b + bb*HROWB + kb*16);
                    const ulonglong2 h2v = *(const ulonglong2*)(h2b + bb*HROWB + kb*16);
                    ffma2(a1G0[bb], wa0.x, h1v.x); ffma2(a1G1[bb], wa0.y, h1v.x);
                    ffma2(a1G0[bb], wa1.x, h1v.y); ffma2(a1G1[bb], wa1.y, h1v.y);
                    ffma2(a2G0[bb], wb0.x, h1v.x); ffma2(a2G1[bb], wb0.y, h1v.x);
                    ffma2(a2G0[bb], wb1.x, h1v.y); ffma2(a2G1[bb], wb1.y, h1v.y);
                    ffma2(a2G0[bb], wc0.x, h2v.x); ffma2(a2G1[bb], wc0.y, h2v.x);
                    ffma2(a2G0[bb], wc1.x, h2v.y); ffma2(a2G1[bb], wc1.y, h2v.y);
                }
            }
        }

        char* h1n = sm + H1_B + cur*HBUF;
        char* h2n = sm + H2_B + prv*HBUF;

        if (t > 0 && t < TT) {
            // pack {gate0,gate1}: horizontal k-parity add
            ull p1[NBI], p2[NBI];
            #pragma unroll
            for (int bb = 0; bb < NBI; ++bb) {
                float2 u0 = unpk(a1G0[bb]), u1 = unpk(a1G1[bb]);
                float2 v0 = unpk(a2G0[bb]), v1 = unpk(a2G1[bb]);
                p1[bb] = pk2(u0.x + u0.y, u1.x + u1.y);
                p2[bb] = pk2(v0.x + v0.y, v1.x + v1.y);
            }
            // kh combine (xor 1): full k sums in packed domain
            #pragma unroll
            for (int bb = 0; bb < NBI; ++bb) {
                p1[bb] = add2(p1[bb], __shfl_xor_sync(0xFFFFFFFFu, p1[bb], 1));
                p2[bb] = add2(p2[bb], __shfl_xor_sync(0xFFFFFFFFu, p2[bb], 1));
            }
            // gate-pair exchange (xor 2); thread finishes bb = gp*4 + kh*2 + oo
            #pragma unroll
            for (int oo = 0; oo < 2; ++oo) {
                const int o  = kh*2 + oo;
                const int ob = gp*4 + o;
                const int sb = (gp^1)*4 + o;
                ull r1 = __shfl_xor_sync(0xFFFFFFFFu, p1[sb], 2);
                ull r2 = __shfl_xor_sync(0xFFFFFFFFu, p2[sb], 2);
                float2 IF1 = unpk(gp ? r1 : p1[ob]);
                float2 GO1 = unpk(gp ? p1[ob] : r1);
                float2 IF2 = unpk(gp ? r2 : p2[ob]);
                float2 GO2 = unpk(gp ? p2[ob] : r2);
                float iv1 = fsig(IF1.x), iv2 = fsig(IF2.x);
                float fv1 = fsig(IF1.y), fv2 = fsig(IF2.y);
                float gv1 = ftanh_(GO1.x), gv2 = ftanh_(GO2.x);
                float ov1 = fsig(GO1.y),  ov2 = fsig(GO2.y);
                c1[oo] = fmaf(fv1, c1[oo], iv1 * gv1);
                c2[oo] = fmaf(fv2, c2[oo], iv2 * gv2);
                const int hoff = (grp*8 + ob)*HROWB + j*4;
                *(float*)(h1n + hoff) = ov1 * ftanh_(c1[oo]);
                *(float*)(h2n + hoff) = ov2 * ftanh_(c2[oo]);
            }
        } else if (t < TT) {
            // t == 0: layer1 only
            ull p1[NBI];
            #pragma unroll
            for (int bb = 0; bb < NBI; ++bb) {
                float2 u0 = unpk(a1G0[bb]), u1 = unpk(a1G1[bb]);
                p1[bb] = pk2(u0.x + u0.y, u1.x + u1.y);
            }
            #pragma unroll
            for (int bb = 0; bb < NBI; ++bb)
                p1[bb] = add2(p1[bb], __shfl_xor_sync(0xFFFFFFFFu, p1[bb], 1));
            #pragma unroll
            for (int oo = 0; oo < 2; ++oo) {
                const int o  = kh*2 + oo;
                const int ob = gp*4 + o;
                const int sb = (gp^1)*4 + o;
                ull r1 = __shfl_xor_sync(0xFFFFFFFFu, p1[sb], 2);
                float2 IF = unpk(gp ? r1 : p1[ob]);
                float2 GO = unpk(gp ? p1[ob] : r1);
                float iv = fsig(IF.x), fv = fsig(IF.y);
                float gv = ftanh_(GO.x), ov = fsig(GO.y);
                c1[oo] = fmaf(fv, c1[oo], iv * gv);
                *(float*)(h1n + (grp*8 + ob)*HROWB + j*4) = ov * ftanh_(c1[oo]);
            }
        } else {
            // t == TT: layer2 only
            ull p2[NBI];
            #pragma unroll
            for (int bb = 0; bb < NBI; ++bb) {
                float2 v0 = unpk(a2G0[bb]), v1 = unpk(a2G1[bb]);
                p2[bb] = pk2(v0.x + v0.y, v1.x + v1.y);
            }
            #pragma unroll
            for (int bb = 0; bb < NBI; ++bb)
                p2[bb] = add2(p2[bb], __shfl_xor_sync(0xFFFFFFFFu, p2[bb], 1));
            #pragma unroll
            for (int oo = 0; oo < 2; ++oo) {
                const int o  = kh*2 + oo;
                const int ob = gp*4 + o;
                const int sb = (gp^1)*4 + o;
                ull r2 = __shfl_xor_sync(0xFFFFFFFFu, p2[sb], 2);
                float2 IF = unpk(gp ? r2 : p2[ob]);
                float2 GO = unpk(gp ? p2[ob] : r2);
                float iv = fsig(IF.x), fv = fsig(IF.y);
                float gv = ftanh_(GO.x), ov = fsig(GO.y);
                c2[oo] = fmaf(fv, c2[oo], iv * gv);
                *(float*)(h2n + (grp*8 + ob)*HROWB + j*4) = ov * ftanh_(c2[oo]);
            }
        }

        if (t + 1 < TT && xact)
            *(float*)(sm + XD_B + prv*XBUF + xoff) = xpre;

        d_bar(barid);
    }

    __syncthreads();
    // ===== final FC + sigmoid: h2[511] in buf 1 =====
    if (tid < NB) {
        const float* h2f = (const float*)(sm + H2_B + HBUF + tid*HROWB);
        float acc = fcb[0];
        #pragma unroll
        for (int jj = 0; jj < HH; ++jj)
            acc = fmaf(h2f[jj], fcw[jj], acc);
        out[blockIdx.x * NB + tid] = fsig(acc);
    }
}

extern "C" void kernel_launch(void* const* d_in, const int* in_sizes, int n_in,
                              void* d_out, int out_size) {
    (void)in_sizes; (void)n_in; (void)out_size;
    cudaFuncSetAttribute(lstm2_kernel,
                         cudaFuncAttributeMaxDynamicSharedMemorySize, SMEM_BYTES);
    lstm2_kernel<<<NCTA, NTHREADS, SMEM_BYTES>>>(
        (const float*)d_in[0],
        (const float*)d_in[1], (const float*)d_in[2],
        (const float*)d_in[3], (const float*)d_in[4],
        (const float*)d_in[5], (const float*)d_in[6],
        (const float*)d_in[7], (const float*)d_in[8],
        (const float*)d_in[9], (const float*)d_in[10],
        (float*)d_out);
}

// round 14
// speedup vs baseline: 1.3020x; 1.2149x over previous
#include <cuda_runtime.h>

// Problem constants
#define TT 512
#define DD 16
#define HH 48
#define NB 16
#define NBI 4
#define NTHREADS 384
#define NCTA 128

typedef unsigned long long ull;

// SMEM byte offsets
#define W1I_B 0                   // [8 kp][96 jj2][16B]
#define WR_B  12288               // [24 kp][96 jj2][3 mat][16B]
#define BB1_B 122880              // [96 jj2][16B] {b_g0,0,b_g1,0}
#define BB2_B 124416
#define H1_B  125952              // [2 buf][16 bb][48f]
#define H2_B  132096
#define XD_B  138240              // [2 buf][16 bb][16f]
#define SMEM_BYTES 140288

#define HROWB 192
#define HBUF  3072
#define XROWB 64
#define XBUF  1024

__device__ __forceinline__ float fsig(float x) {
    return __fdividef(1.0f, 1.0f + __expf(-x));
}
__device__ __forceinline__ float ftanh_(float x) {
    return __fdividef(2.0f, 1.0f + __expf(-2.0f * x)) - 1.0f;
}
__device__ __forceinline__ void ffma2(ull& a, ull w, ull h) {
    asm("fma.rn.f32x2 %0, %1, %2, %0;" : "+l"(a) : "l"(w), "l"(h));
}
__device__ __forceinline__ float2 unpk(ull v) {
    float2 r;
    asm("mov.b64 {%0, %1}, %2;" : "=f"(r.x), "=f"(r.y) : "l"(v));
    return r;
}
__device__ __forceinline__ ull pk2(float a, float b) {
    ull d;
    asm("mov.b64 %0, {%1, %2};" : "=l"(d) : "f"(a), "f"(b));
    return d;
}
__device__ __forceinline__ void q_bar(int id) {
    asm volatile("bar.sync %0, 96;" :: "r"(id) : "memory");
}

__global__ void __launch_bounds__(NTHREADS, 1)
lstm2_kernel(const float* __restrict__ x,
             const float* __restrict__ Wih0, const float* __restrict__ Whh0,
             const float* __restrict__ bih0, const float* __restrict__ bhh0,
             const float* __restrict__ Wih1, const float* __restrict__ Whh1,
             const float* __restrict__ bih1, const float* __restrict__ bhh1,
             const float* __restrict__ fcw,  const float* __restrict__ fcb,
             float* __restrict__ out)
{
    extern __shared__ char sm[];
    float* smf = (float*)sm;
    const int tid = threadIdx.x;

    // ---- repack W1I: [8kp][96jj2][16B] ----
    for (int i = tid; i < 8*96*4; i += NTHREADS) {
        int f = i & 3, jj2 = (i >> 2) % 96, kp = i / 384;
        int jx = jj2 >> 1, gpx = jj2 & 1;
        int gate = gpx*2 + (f >> 1), k = kp*2 + (f & 1);
        smf[(W1I_B >> 2) + i] = Wih0[(gate*HH + jx)*DD + k];
    }
    // ---- repack WR: [24kp][96jj2][3mat][16B] (Whh0, Wih1, Whh1) ----
    for (int i = tid; i < 24*96*3*4; i += NTHREADS) {
        int f = i & 3, m = (i >> 2) % 3, jj2 = (i / 12) % 96, kp = i / 1152;
        int jx = jj2 >> 1, gpx = jj2 & 1;
        int gate = gpx*2 + (f >> 1), k = kp*2 + (f & 1);
        int r = (gate*HH + jx)*HH + k;
        smf[(WR_B >> 2) + i] = (m == 0) ? Whh0[r] : (m == 1) ? Wih1[r] : Whh1[r];
    }
    // ---- biases ----
    for (int i = tid; i < 96*4; i += NTHREADS) {
        int f = i & 3, jj2 = i >> 2;
        int jx = jj2 >> 1, gpx = jj2 & 1;
        int gate = gpx*2 + (f >> 1);
        float v1 = (f & 1) ? 0.f : (bih0[gate*HH + jx] + bhh0[gate*HH + jx]);
        float v2 = (f & 1) ? 0.f : (bih1[gate*HH + jx] + bhh1[gate*HH + jx]);
        smf[(BB1_B >> 2) + i] = v1;
        smf[(BB2_B >> 2) + i] = v2;
    }
    // ---- zero h region ----
    for (int i = tid; i < (4*HBUF) >> 2; i += NTHREADS)
        smf[(H1_B >> 2) + i] = 0.f;

    // ---- quarter decomposition (R10 champion): 4 domains of 3 warps ----
    const int w    = tid >> 5;
    const int lane = tid & 31;
    const int q    = w / 3;
    const int wq   = w % 3;
    const int gp   = lane & 1;
    const int j    = wq * 16 + (lane >> 1);
    const int jj2  = j * 2 + gp;
    const int grp  = q;
    const int barid = 1 + q;
    const int qtid  = wq * 32 + lane;

    const float* xg = x + ((long)blockIdx.x * NB) * (long)(TT*DD);
    const int xact = (qtid < 64);
    const int xb_  = q * 4 + (qtid >> 4);
    const int xd   = qtid & 15;
    const int xoff = xb_ * XROWB + xd * 4;

    if (xact)
        *(float*)(sm + XD_B + xoff) = xg[(long)xb_*(TT*DD) + xd];
    __syncthreads();

    const char* pWI = sm + W1I_B + jj2*16;
    const char* pWR = sm + WR_B + jj2*48;
    const ulonglong2 b1 = *(const ulonglong2*)(sm + BB1_B + jj2*16);
    const ulonglong2 b2 = *(const ulonglong2*)(sm + BB2_B + jj2*16);

    float c1[2] = {0.f, 0.f};
    float c2[2] = {0.f, 0.f};
    const int hsoff = grp*4*HROWB;

    for (int t = 0; t <= TT; ++t) {
        const int cur = t & 1, prv = cur ^ 1;

        float xpre = 0.f;
        if (t + 1 < TT && xact)
            xpre = xg[(long)xb_*(TT*DD) + (long)(t+1)*DD + xd];

        ull a1I[NBI], a1F[NBI], a2I[NBI], a2F[NBI];
        #pragma unroll
        for (int bb = 0; bb < NBI; ++bb) {
            a1I[bb] = b1.x; a1F[bb] = b1.y;
            a2I[bb] = b2.x; a2F[bb] = b2.y;
        }

        // ===== layer1 input: x — w-major order (4 consecutive ffma2 share w) =====
        {
            const char* xb = sm + XD_B + cur*XBUF + grp*4*XROWB;
            #pragma unroll
            for (int kx = 0; kx < 4; ++kx) {
                const ulonglong2 w0 = *(const ulonglong2*)(pWI + (2*kx  )*1536);
                const ulonglong2 w1 = *(const ulonglong2*)(pWI + (2*kx+1)*1536);
                ulonglong2 xv[NBI];
                #pragma unroll
                for (int bb = 0; bb < NBI; ++bb)
                    xv[bb] = *(const ulonglong2*)(xb + bb*XROWB + kx*16);
                #pragma unroll
                for (int bb = 0; bb < NBI; ++bb) ffma2(a1I[bb], w0.x, xv[bb].x);
                #pragma unroll
                for (int bb = 0; bb < NBI; ++bb) ffma2(a1F[bb], w0.y, xv[bb].x);
                #pragma unroll
                for (int bb = 0; bb < NBI; ++bb) ffma2(a1I[bb], w1.x, xv[bb].y);
                #pragma unroll
                for (int bb = 0; bb < NBI; ++bb) ffma2(a1F[bb], w1.y, xv[bb].y);
            }
        }

        // ===== fused recurrent — w-major order for .reuse on the w operand =====
        {
            const char* h1b = sm + H1_B + prv*HBUF + hsoff;
            const char* h2b = sm + H2_B + cur*HBUF + hsoff;
            #pragma unroll 2
            for (int kb = 0; kb < 12; ++kb) {
                const char* wb = pWR + kb*9216;
                const ulonglong2 wa0 = *(const ulonglong2*)(wb);
                const ulonglong2 wb0 = *(const ulonglong2*)(wb + 16);
                const ulonglong2 wc0 = *(const ulonglong2*)(wb + 32);
                const ulonglong2 wa1 = *(const ulonglong2*)(wb + 4608);
                const ulonglong2 wb1 = *(const ulonglong2*)(wb + 4624);
                const ulonglong2 wc1 = *(const ulonglong2*)(wb + 4640);
                ulonglong2 h1v[NBI], h2v[NBI];
                #pragma unroll
                for (int bb = 0; bb < NBI; ++bb) {
                    h1v[bb] = *(const ulonglong2*)(h1b + bb*HROWB + kb*16);
                    h2v[bb] = *(const ulonglong2*)(h2b + bb*HROWB + kb*16);
                }
                // 12 groups of 4: within each group the w register repeats -> .reuse
                #pragma unroll
                for (int bb = 0; bb < NBI; ++bb) ffma2(a1I[bb], wa0.x, h1v[bb].x);
                #pragma unroll
                for (int bb = 0; bb < NBI; ++bb) ffma2(a1F[bb], wa0.y, h1v[bb].x);
                #pragma unroll
                for (int bb = 0; bb < NBI; ++bb) ffma2(a1I[bb], wa1.x, h1v[bb].y);
                #pragma unroll
                for (int bb = 0; bb < NBI; ++bb) ffma2(a1F[bb], wa1.y, h1v[bb].y);
                #pragma unroll
                for (int bb = 0; bb < NBI; ++bb) ffma2(a2I[bb], wb0.x, h1v[bb].x);
                #pragma unroll
                for (int bb = 0; bb < NBI; ++bb) ffma2(a2F[bb], wb0.y, h1v[bb].x);
                #pragma unroll
                for (int bb = 0; bb < NBI; ++bb) ffma2(a2I[bb], wb1.x, h1v[bb].y);
                #pragma unroll
                for (int bb = 0; bb < NBI; ++bb) ffma2(a2F[bb], wb1.y, h1v[bb].y);
                #pragma unroll
                for (int bb = 0; bb < NBI; ++bb) ffma2(a2I[bb], wc0.x, h2v[bb].x);
                #pragma unroll
                for (int bb = 0; bb < NBI; ++bb) ffma2(a2F[bb], wc0.y, h2v[bb].x);
                #pragma unroll
                for (int bb = 0; bb < NBI; ++bb) ffma2(a2I[bb], wc1.x, h2v[bb].y);
                #pragma unroll
                for (int bb = 0; bb < NBI; ++bb) ffma2(a2F[bb], wc1.y, h2v[bb].y);
            }
        }

        char* h1n = sm + H1_B + cur*HBUF;
        char* h2n = sm + H2_B + prv*HBUF;

        if (t > 0 && t < TT) {
            ull p1[NBI], e1[NBI], p2[NBI], e2[NBI];
            #pragma unroll
            for (int bb = 0; bb < NBI; ++bb) {
                float2 v1I = unpk(a1I[bb]), v1F = unpk(a1F[bb]);
                float2 v2I = unpk(a2I[bb]), v2F = unpk(a2F[bb]);
                p1[bb] = pk2(v1I.x + v1I.y, v1F.x + v1F.y);
                p2[bb] = pk2(v2I.x + v2I.y, v2F.x + v2F.y);
            }
            #pragma unroll
            for (int bb = 0; bb < NBI; ++bb) {
                e1[bb] = __shfl_xor_sync(0xFFFFFFFFu, p1[bb], 1);
                e2[bb] = __shfl_xor_sync(0xFFFFFFFFu, p2[bb], 1);
            }
            #pragma unroll
            for (int o = 0; o < 2; ++o) {
                const int bb = gp*2 + o;
                float2 pIF1 = unpk(gp ? e1[bb] : p1[bb]);
                float2 pGO1 = unpk(gp ? p1[bb] : e1[bb]);
                float2 pIF2 = unpk(gp ? e2[bb] : p2[bb]);
                float2 pGO2 = unpk(gp ? p2[bb] : e2[bb]);
                float iv1 = fsig(pIF1.x), iv2 = fsig(pIF2.x);
                float fv1 = fsig(pIF1.y), fv2 = fsig(pIF2.y);
                float gv1 = ftanh_(pGO1.x), gv2 = ftanh_(pGO2.x);
                float ov1 = fsig(pGO1.y),  ov2 = fsig(pGO2.y);
                c1[o] = fmaf(fv1, c1[o], iv1 * gv1);
                c2[o] = fmaf(fv2, c2[o], iv2 * gv2);
                *(float*)(h1n + hsoff + bb*HROWB + j*4) = ov1 * ftanh_(c1[o]);
                *(float*)(h2n + hsoff + bb*HROWB + j*4) = ov2 * ftanh_(c2[o]);
            }
        } else if (t < TT) {
            ull p1[NBI], e1[NBI];
            #pragma unroll
            for (int bb = 0; bb < NBI; ++bb) {
                float2 vI = unpk(a1I[bb]), vF = unpk(a1F[bb]);
                p1[bb] = pk2(vI.x + vI.y, vF.x + vF.y);
            }
            #pragma unroll
            for (int bb = 0; bb < NBI; ++bb)
                e1[bb] = __shfl_xor_sync(0xFFFFFFFFu, p1[bb], 1);
            #pragma unroll
            for (int o = 0; o < 2; ++o) {
                const int bb = gp*2 + o;
                float2 pIF = unpk(gp ? e1[bb] : p1[bb]);
                float2 pGO = unpk(gp ? p1[bb] : e1[bb]);
                float iv = fsig(pIF.x), fv = fsig(pIF.y);
                float gv = ftanh_(pGO.x), ov = fsig(pGO.y);
                c1[o] = fmaf(fv, c1[o], iv * gv);
                *(float*)(h1n + hsoff + bb*HROWB + j*4) = ov * ftanh_(c1[o]);
            }
        } else {
            ull p2[NBI], e2[NBI];
            #pragma unroll
            for (int bb = 0; bb < NBI; ++bb) {
                float2 vI = unpk(a2I[bb]), vF = unpk(a2F[bb]);
                p2[bb] = pk2(vI.x + vI.y, vF.x + vF.y);
            }
            #pragma unroll
            for (int bb = 0; bb < NBI; ++bb)
                e2[bb] = __shfl_xor_sync(0xFFFFFFFFu, p2[bb], 1);
            #pragma unroll
            for (int o = 0; o < 2; ++o) {
                const int bb = gp*2 + o;
                float2 pIF = unpk(gp ? e2[bb] : p2[bb]);
                float2 pGO = unpk(gp ? p2[bb] : e2[bb]);
                float iv = fsig(pIF.x), fv = fsig(pIF.y);
                float gv = ftanh_(pGO.x), ov = fsig(pGO.y);
                c2[o] = fmaf(fv, c2[o], iv * gv);
                *(float*)(h2n + hsoff + bb*HROWB + j*4) = ov * ftanh_(c2[o]);
            }
        }

        if (t + 1 < TT && xact)
            *(float*)(sm + XD_B + prv*XBUF + xoff) = xpre;

        q_bar(barid);
    }

    __syncthreads();
    // ===== final FC + sigmoid: h2[511] in buf 1 =====
    if (tid < NB) {
        const float* h2f = (const float*)(sm + H2_B + HBUF + tid*HROWB);
        float acc = fcb[0];
        #pragma unroll
        for (int jj = 0; jj < HH; ++jj)
            acc = fmaf(h2f[jj], fcw[jj], acc);
        out[blockIdx.x * NB + tid] = fsig(acc);
    }
}

extern "C" void kernel_launch(void* const* d_in, const int* in_sizes, int n_in,
                              void* d_out, int out_size) {
    (void)in_sizes; (void)n_in; (void)out_size;
    cudaFuncSetAttribute(lstm2_kernel,
                         cudaFuncAttributeMaxDynamicSharedMemorySize, SMEM_BYTES);
    lstm2_kernel<<<NCTA, NTHREADS, SMEM_BYTES>>>(
        (const float*)d_in[0],
        (const float*)d_in[1], (const float*)d_in[2],
        (const float*)d_in[3], (const float*)d_in[4],
        (const float*)d_in[5], (const float*)d_in[6],
        (const float*)d_in[7], (const float*)d_in[8],
        (const float*)d_in[9], (const float*)d_in[10],
        (float*)d_out);
}

// round 15
// speedup vs baseline: 1.3632x; 1.0470x over previous
#include <cuda_runtime.h>

// Problem constants
#define TT 512
#define DD 16
#define HH 48
#define BTOT 2048
#define NTHREADS 384
#define NCTA 152       // one CTA per SM on GB300 (152 SMs); 13-14 batch rows each

typedef unsigned long long ull;

// SMEM byte offsets
#define W1I_B 0                   // [8 kp][96 jj2][16B]
#define WR_B  12288               // [24 kp][96 jj2][3 mat][16B]
#define BB1_B 122880              // [96 jj2][16B] {b_g0,0,b_g1,0}
#define BB2_B 124416
#define H1_B  125952              // [2 buf][16 row][48f]
#define H2_B  132096
#define XD_B  138240              // [2 buf][16 row][16f]
#define SMEM_BYTES 140288

#define HROWB 192
#define HBUF  3072
#define XROWB 64
#define XBUF  1024

__device__ __forceinline__ float fsig(float x) {
    return __fdividef(1.0f, 1.0f + __expf(-x));
}
__device__ __forceinline__ float ftanh_(float x) {
    return __fdividef(2.0f, 1.0f + __expf(-2.0f * x)) - 1.0f;
}
__device__ __forceinline__ void ffma2(ull& a, ull w, ull h) {
    asm("fma.rn.f32x2 %0, %1, %2, %0;" : "+l"(a) : "l"(w), "l"(h));
}
__device__ __forceinline__ float2 unpk(ull v) {
    float2 r;
    asm("mov.b64 {%0, %1}, %2;" : "=f"(r.x), "=f"(r.y) : "l"(v));
    return r;
}
__device__ __forceinline__ ull pk2(float a, float b) {
    ull d;
    asm("mov.b64 %0, {%1, %2};" : "=l"(d) : "f"(a), "f"(b));
    return d;
}
__device__ __forceinline__ void q_bar(int id) {
    asm volatile("bar.sync %0, 96;" :: "r"(id) : "memory");
}

// Main recurrence, templated on rows-per-domain (3 or 4).
template<int NBA>
__device__ __forceinline__ void run_loop(
    char* sm, const float* xgp, int xact, int xoff,
    const char* pWI, const char* pWR,
    const ulonglong2 b1, const ulonglong2 b2,
    const int gp, const int j, const int barid,
    const int hsoff, const int xsoff)
{
    float c1[2] = {0.f, 0.f};
    float c2[2] = {0.f, 0.f};

    // stage x[0] for this domain
    if (xact) *(float*)(sm + XD_B + xoff) = xgp[0];
    q_bar(barid);

    for (int t = 0; t <= TT; ++t) {
        const int cur = t & 1, prv = cur ^ 1;

        float xpre = 0.f;
        if (t + 1 < TT && xact)
            xpre = xgp[(t + 1) * DD];

        ull a1I[NBA], a1F[NBA], a2I[NBA], a2F[NBA];
        #pragma unroll
        for (int bb = 0; bb < NBA; ++bb) {
            a1I[bb] = b1.x; a1F[bb] = b1.y;
            a2I[bb] = b2.x; a2F[bb] = b2.y;
        }

        // ===== layer1 input: x =====
        {
            const char* xb = sm + XD_B + cur*XBUF + xsoff;
            #pragma unroll
            for (int kx = 0; kx < 4; ++kx) {
                const ulonglong2 w0 = *(const ulonglong2*)(pWI + (2*kx  )*1536);
                const ulonglong2 w1 = *(const ulonglong2*)(pWI + (2*kx+1)*1536);
                #pragma unroll
                for (int bb = 0; bb < NBA; ++bb) {
                    const ulonglong2 xv = *(const ulonglong2*)(xb + bb*XROWB + kx*16);
                    ffma2(a1I[bb], w0.x, xv.x); ffma2(a1F[bb], w0.y, xv.x);
                    ffma2(a1I[bb], w1.x, xv.y); ffma2(a1F[bb], w1.y, xv.y);
                }
            }
        }

        // ===== fused recurrent: W1R@h1[t-1], W2I@h1[t-1], W2R@h2[t-2] =====
        {
            const char* h1b = sm + H1_B + prv*HBUF + hsoff;
            const char* h2b = sm + H2_B + cur*HBUF + hsoff;
            #pragma unroll 4
            for (int kb = 0; kb < 12; ++kb) {
                const char* wb = pWR + kb*9216;
                const ulonglong2 wa0 = *(const ulonglong2*)(wb);
                const ulonglong2 wb0 = *(const ulonglong2*)(wb + 16);
                const ulonglong2 wc0 = *(const ulonglong2*)(wb + 32);
                const ulonglong2 wa1 = *(const ulonglong2*)(wb + 4608);
                const ulonglong2 wb1 = *(const ulonglong2*)(wb + 4624);
                const ulonglong2 wc1 = *(const ulonglong2*)(wb + 4640);
                #pragma unroll
                for (int bb = 0; bb < NBA; ++bb) {
                    const ulonglong2 h1v = *(const ulonglong2*)(h1b + bb*HROWB + kb*16);
                    const ulonglong2 h2v = *(const ulonglong2*)(h2b + bb*HROWB + kb*16);
                    ffma2(a1I[bb], wa0.x, h1v.x); ffma2(a1F[bb], wa0.y, h1v.x);
                    ffma2(a1I[bb], wa1.x, h1v.y); ffma2(a1F[bb], wa1.y, h1v.y);
                    ffma2(a2I[bb], wb0.x, h1v.x); ffma2(a2F[bb], wb0.y, h1v.x);
                    ffma2(a2I[bb], wb1.x, h1v.y); ffma2(a2F[bb], wb1.y, h1v.y);
                    ffma2(a2I[bb], wc0.x, h2v.x); ffma2(a2F[bb], wc0.y, h2v.x);
                    ffma2(a2I[bb], wc1.x, h2v.y); ffma2(a2F[bb], wc1.y, h2v.y);
                }
            }
        }

        char* h1n = sm + H1_B + cur*HBUF + hsoff;
        char* h2n = sm + H2_B + prv*HBUF + hsoff;

        if (t > 0 && t < TT) {
            ull p1[NBA], e1[NBA], p2[NBA], e2[NBA];
            #pragma unroll
            for (int bb = 0; bb < NBA; ++bb) {
                float2 v1I = unpk(a1I[bb]), v1F = unpk(a1F[bb]);
                float2 v2I = unpk(a2I[bb]), v2F = unpk(a2F[bb]);
                p1[bb] = pk2(v1I.x + v1I.y, v1F.x + v1F.y);
                p2[bb] = pk2(v2I.x + v2I.y, v2F.x + v2F.y);
            }
            #pragma unroll
            for (int bb = 0; bb < NBA; ++bb) {
                e1[bb] = __shfl_xor_sync(0xFFFFFFFFu, p1[bb], 1);
                e2[bb] = __shfl_xor_sync(0xFFFFFFFFu, p2[bb], 1);
            }
            #pragma unroll
            for (int o = 0; o < 2; ++o) {
                const int bb = gp*2 + o;
                if (bb < NBA) {
                    float2 pIF1 = unpk(gp ? e1[bb] : p1[bb]);
                    float2 pGO1 = unpk(gp ? p1[bb] : e1[bb]);
                    float2 pIF2 = unpk(gp ? e2[bb] : p2[bb]);
                    float2 pGO2 = unpk(gp ? p2[bb] : e2[bb]);
                    float iv1 = fsig(pIF1.x), iv2 = fsig(pIF2.x);
                    float fv1 = fsig(pIF1.y), fv2 = fsig(pIF2.y);
                    float gv1 = ftanh_(pGO1.x), gv2 = ftanh_(pGO2.x);
                    float ov1 = fsig(pGO1.y),  ov2 = fsig(pGO2.y);
                    c1[o] = fmaf(fv1, c1[o], iv1 * gv1);
                    c2[o] = fmaf(fv2, c2[o], iv2 * gv2);
                    *(float*)(h1n + bb*HROWB + j*4) = ov1 * ftanh_(c1[o]);
                    *(float*)(h2n + bb*HROWB + j*4) = ov2 * ftanh_(c2[o]);
                }
            }
        } else if (t < TT) {
            ull p1[NBA], e1[NBA];
            #pragma unroll
            for (int bb = 0; bb < NBA; ++bb) {
                float2 vI = unpk(a1I[bb]), vF = unpk(a1F[bb]);
                p1[bb] = pk2(vI.x + vI.y, vF.x + vF.y);
            }
            #pragma unroll
            for (int bb = 0; bb < NBA; ++bb)
                e1[bb] = __shfl_xor_sync(0xFFFFFFFFu, p1[bb], 1);
            #pragma unroll
            for (int o = 0; o < 2; ++o) {
                const int bb = gp*2 + o;
                if (bb < NBA) {
                    float2 pIF = unpk(gp ? e1[bb] : p1[bb]);
                    float2 pGO = unpk(gp ? p1[bb] : e1[bb]);
                    float iv = fsig(pIF.x), fv = fsig(pIF.y);
                    float gv = ftanh_(pGO.x), ov = fsig(pGO.y);
                    c1[o] = fmaf(fv, c1[o], iv * gv);
                    *(float*)(h1n + bb*HROWB + j*4) = ov * ftanh_(c1[o]);
                }
            }
        } else {
            ull p2[NBA], e2[NBA];
            #pragma unroll
            for (int bb = 0; bb < NBA; ++bb) {
                float2 vI = unpk(a2I[bb]), vF = unpk(a2F[bb]);
                p2[bb] = pk2(vI.x + vI.y, vF.x + vF.y);
            }
            #pragma unroll
            for (int bb = 0; bb < NBA; ++bb)
                e2[bb] = __shfl_xor_sync(0xFFFFFFFFu, p2[bb], 1);
            #pragma unroll
            for (int o = 0; o < 2; ++o) {
                const int bb = gp*2 + o;
                if (bb < NBA) {
                    float2 pIF = unpk(gp ? e2[bb] : p2[bb]);
                    float2 pGO = unpk(gp ? p2[bb] : e2[bb]);
                    float iv = fsig(pIF.x), fv = fsig(pIF.y);
                    float gv = ftanh_(pGO.x), ov = fsig(pGO.y);
                    c2[o] = fmaf(fv, c2[o], iv * gv);
                    *(float*)(h2n + bb*HROWB + j*4) = ov * ftanh_(c2[o]);
                }
            }
        }

        if (t + 1 < TT && xact)
            *(float*)(sm + XD_B + prv*XBUF + xoff) = xpre;

        q_bar(barid);
    }
}

__global__ void __launch_bounds__(NTHREADS, 1)
lstm2_kernel(const float* __restrict__ x,
             const float* __restrict__ Wih0, const float* __restrict__ Whh0,
             const float* __restrict__ bih0, const float* __restrict__ bhh0,
             const float* __restrict__ Wih1, const float* __restrict__ Whh1,
             const float* __restrict__ bih1, const float* __restrict__ bhh1,
             const float* __restrict__ fcw,  const float* __restrict__ fcb,
             float* __restrict__ out)
{
    extern __shared__ char sm[];
    float* smf = (float*)sm;
    const int tid = threadIdx.x;

    // ---- repack W1I: [8kp][96jj2][16B] ----
    for (int i = tid; i < 8*96*4; i += NTHREADS) {
        int f = i & 3, jj2 = (i >> 2) % 96, kp = i / 384;
        int jx = jj2 >> 1, gpx = jj2 & 1;
        int gate = gpx*2 + (f >> 1), k = kp*2 + (f & 1);
        smf[(W1I_B >> 2) + i] = Wih0[(gate*HH + jx)*DD + k];
    }
    // ---- repack WR: [24kp][96jj2][3mat][16B] (Whh0, Wih1, Whh1) ----
    for (int i = tid; i < 24*96*3*4; i += NTHREADS) {
        int f = i & 3, m = (i >> 2) % 3, jj2 = (i / 12) % 96, kp = i / 1152;
        int jx = jj2 >> 1, gpx = jj2 & 1;
        int gate = gpx*2 + (f >> 1), k = kp*2 + (f & 1);
        int r = (gate*HH + jx)*HH + k;
        smf[(WR_B >> 2) + i] = (m == 0) ? Whh0[r] : (m == 1) ? Wih1[r] : Whh1[r];
    }
    // ---- biases ----
    for (int i = tid; i < 96*4; i += NTHREADS) {
        int f = i & 3, jj2 = i >> 2;
        int jx = jj2 >> 1, gpx = jj2 & 1;
        int gate = gpx*2 + (f >> 1);
        float v1 = (f & 1) ? 0.f : (bih0[gate*HH + jx] + bhh0[gate*HH + jx]);
        float v2 = (f & 1) ? 0.f : (bih1[gate*HH + jx] + bhh1[gate*HH + jx]);
        smf[(BB1_B >> 2) + i] = v1;
        smf[(BB2_B >> 2) + i] = v2;
    }
    // ---- zero h region ----
    for (int i = tid; i < (4*HBUF) >> 2; i += NTHREADS)
        smf[(H1_B >> 2) + i] = 0.f;

    // ---- batch split over 152 CTAs: 13 or 14 rows each ----
    const int rs = (blockIdx.x * BTOT) / NCTA;
    const int re = ((blockIdx.x + 1) * BTOT) / NCTA;
    const int nb = re - rs;

    // ---- quarter decomposition: 4 domains of 3 warps ----
    const int w    = tid >> 5;
    const int lane = tid & 31;
    const int q    = w / 3;
    const int wq   = w % 3;
    const int gp   = lane & 1;
    const int j    = wq * 16 + (lane >> 1);
    const int jj2  = j * 2 + gp;
    const int barid = 1 + q;
    const int qtid  = wq * 32 + lane;

    // domain's local row range
    const int ds  = (q * nb) >> 2;
    const int de  = ((q + 1) * nb) >> 2;
    const int nba = de - ds;           // 3 or 4

    // x staging assignment within the domain
    const int xrowl = ds + (qtid >> 4);           // local row this thread stages
    const int xact  = (qtid >> 4) < nba;
    const int xd    = qtid & 15;
    const int xoff  = xrowl * XROWB + xd * 4;
    const float* xgp = x + (long)(rs + xrowl) * (long)(TT * DD) + xd;

    const char* pWI = sm + W1I_B + jj2*16;
    const char* pWR = sm + WR_B + jj2*48;

    __syncthreads();

    const ulonglong2 b1 = *(const ulonglong2*)(sm + BB1_B + jj2*16);
    const ulonglong2 b2 = *(const ulonglong2*)(sm + BB2_B + jj2*16);
    const int hsoff = ds * HROWB;
    const int xsoff = ds * XROWB;

    if (nba == 4)
        run_loop<4>(sm, xgp, xact, xoff, pWI, pWR, b1, b2, gp, j, barid, hsoff, xsoff);
    else
        run_loop<3>(sm, xgp, xact, xoff, pWI, pWR, b1, b2, gp, j, barid, hsoff, xsoff);

    __syncthreads();
    // ===== final FC + sigmoid: h2[511] in buf 1 =====
    if (tid < nb) {
        const float* h2f = (const float*)(sm + H2_B + HBUF + tid*HROWB);
        float acc = fcb[0];
        #pragma unroll
        for (int jj = 0; jj < HH; ++jj)
            acc = fmaf(h2f[jj], fcw[jj], acc);
        out[rs + tid] = fsig(acc);
    }
}

extern "C" void kernel_launch(void* const* d_in, const int* in_sizes, int n_in,
                              void* d_out, int out_size) {
    (void)in_sizes; (void)n_in; (void)out_size;
    cudaFuncSetAttribute(lstm2_kernel,
                         cudaFuncAttributeMaxDynamicSharedMemorySize, SMEM_BYTES);
    lstm2_kernel<<<NCTA, NTHREADS, SMEM_BYTES>>>(
        (const float*)d_in[0],
        (const float*)d_in[1], (const float*)d_in[2],
        (const float*)d_in[3], (const float*)d_in[4],
        (const float*)d_in[5], (const float*)d_in[6],
        (const float*)d_in[7], (const float*)d_in[8],
        (const float*)d_in[9], (const float*)d_in[10],
        (float*)d_out);
}